// round 17
// baseline (speedup 1.0000x reference)
#include <cuda_runtime.h>

// HermiteFuncs: x[B,n,N] -> psi[B,n,R,N], R=6  (B=32, n=64, N=4096)
//   t = tanh(x)*sqrt(13); g = exp(-t^2/2); c = pi^-0.25
//   psi0 = c*g; psi1 = sqrt(2)*c*t*g
//   psi_k = sqrt(2/k)*t*psi_{k-1} - sqrt((k-1)/k)*psi_{k-2}
//
// At the DRAM-write roofline (201 MB compulsory write/replay; input pinned
// in L2 across graph replays). This round: sm_100+ 256-bit global accesses —
// ld.global.nc.L2::evict_last.v8.b32 for the pinned input (no createpolicy
// needed; ptxas accepts the bare hint at v8 width) and st.global.cs.v8.b32
// for the streaming output (half the store instructions, evict-first).

#define R_FUNCS 6
#define SCALE   3.6055512754639896f   /* sqrt(13) */
#define C_PI4   0.7511255444649425f   /* pi^-0.25 */
#define SQRT2   1.4142135623730951f

// a_k = sqrt(2/k), b_k = sqrt((k-1)/k), k = 2..5
__device__ __constant__ float2 RECUR[4] = {
    {1.0000000000000000f, 0.7071067811865476f},  // k=2
    {0.8164965809277260f, 0.8164965809277260f},  // k=3
    {0.7071067811865476f, 0.8660254037844386f},  // k=4
    {0.6324555320336759f, 0.8944271909999159f},  // k=5
};

// 256-bit read-only load, L2 evict-last (pin input across graph replays)
__device__ __forceinline__ void ld_v8_evict_last(const float* p, float r[8]) {
    unsigned u0, u1, u2, u3, u4, u5, u6, u7;
    asm volatile(
        "ld.global.nc.L2::evict_last.v8.b32 {%0,%1,%2,%3,%4,%5,%6,%7}, [%8];"
        : "=r"(u0), "=r"(u1), "=r"(u2), "=r"(u3),
          "=r"(u4), "=r"(u5), "=r"(u6), "=r"(u7)
        : "l"(p));
    r[0] = __uint_as_float(u0); r[1] = __uint_as_float(u1);
    r[2] = __uint_as_float(u2); r[3] = __uint_as_float(u3);
    r[4] = __uint_as_float(u4); r[5] = __uint_as_float(u5);
    r[6] = __uint_as_float(u6); r[7] = __uint_as_float(u7);
}

// 256-bit streaming store (evict-first)
__device__ __forceinline__ void st_v8_cs(float* p, const float r[8]) {
    asm volatile(
        "st.global.cs.v8.b32 [%0], {%1,%2,%3,%4,%5,%6,%7,%8};"
        :: "l"(p),
           "r"(__float_as_uint(r[0])), "r"(__float_as_uint(r[1])),
           "r"(__float_as_uint(r[2])), "r"(__float_as_uint(r[3])),
           "r"(__float_as_uint(r[4])), "r"(__float_as_uint(r[5])),
           "r"(__float_as_uint(r[6])), "r"(__float_as_uint(r[7]))
        : "memory");
}

// One thread per 8 consecutive floats. Row of N=4096 = 512 v8-chunks.
__global__ void __launch_bounds__(256)
hermite_kernel(const float* __restrict__ x, float* __restrict__ out,
               int total_v8) {
    int idx = blockIdx.x * blockDim.x + threadIdx.x;
    if (idx >= total_v8) return;

    float v[8];
    ld_v8_evict_last(x + (long long)idx * 8, v);

    int row = idx >> 9;                // 512 v8 chunks per row
    int col = idx & 511;
    long long base = (long long)row * (R_FUNCS * 4096) + (long long)col * 8;

    float t[8], p0[8], p1[8];
#pragma unroll
    for (int i = 0; i < 8; ++i) {
        t[i] = tanhf(v[i]) * SCALE;
        float g = __expf(-0.5f * t[i] * t[i]);
        p0[i] = C_PI4 * g;
        p1[i] = SQRT2 * C_PI4 * t[i] * g;
    }
    st_v8_cs(out + base, p0);
    st_v8_cs(out + base + 4096, p1);

#pragma unroll
    for (int k = 2; k < R_FUNCS; ++k) {
        float2 ab = RECUR[k - 2];
        float pk[8];
#pragma unroll
        for (int i = 0; i < 8; ++i) {
            pk[i] = ab.x * t[i] * p1[i] - ab.y * p0[i];
            p0[i] = p1[i];
            p1[i] = pk[i];
        }
        st_v8_cs(out + base + (long long)k * 4096, pk);
    }
}

extern "C" void kernel_launch(void* const* d_in, const int* in_sizes, int n_in,
                              void* d_out, int out_size) {
    const float* x = (const float*)d_in[0];
    float* out = (float*)d_out;
    int total_v8 = in_sizes[0] / 8;           // 1,048,576
    int threads = 256;
    int blocks = (total_v8 + threads - 1) / threads;   // 4096
    hermite_kernel<<<blocks, threads>>>(x, out, total_v8);
}